// round 1
// baseline (speedup 1.0000x reference)
#include <cuda_runtime.h>
#include <cstdint>

// Problem constants
#define NIMG   32768
#define HH     6
#define WW     8
#define CC     14
#define CELLS  (NIMG * HH * WW)      // 1,572,864
#define TPB    256
#define TILES  (CELLS / TPB)         // 6144, exact
#define PAD    15                    // stride-15 smem layout: coprime with 32 -> conflict-free

#define LAMBDA_COORD 8.0f
#define LAMBDA_NOOBJ 1.0f
#define LAMBDA_CLASS 0.7f
#define EPSV 1e-10f

__device__ float g_partials[TILES];

__device__ __forceinline__ float iou_f(float x1, float y1, float sw1, float sh1,
                                       float x2, float y2, float sw2, float sh2) {
    float w1 = sw1 * sw1, h1 = sh1 * sh1;
    float w2 = sw2 * sw2, h2 = sh2 * sh2;
    float left  = fmaxf(x1 - 0.5f * w1, x2 - 0.5f * w2);
    float right = fminf(x1 + 0.5f * w1, x2 + 0.5f * w2);
    float top   = fmaxf(y1 - 0.5f * h1, y2 - 0.5f * h2);
    float bot   = fminf(y1 + 0.5f * h1, y2 + 0.5f * h2);
    float inter = fmaxf(right - left, 0.0f) * fmaxf(bot - top, 0.0f);
    float uni   = w1 * h1 + w2 * h2 - inter;
    return inter / (uni + EPSV);
}

__global__ void __launch_bounds__(TPB)
yolo_cell_kernel(const float* __restrict__ out, const float* __restrict__ gt) {
    __shared__ float s_o[TPB * PAD];
    __shared__ float s_g[TPB * PAD];
    __shared__ float red[TPB];

    const unsigned tid  = threadIdx.x;
    const unsigned tile = blockIdx.x;
    const size_t base = (size_t)tile * (TPB * CC);

    // Coalesced load: 14 fully-coalesced passes per tensor, scattered to
    // stride-15 padded smem (compiler emits magic-mul for /14, %14).
#pragma unroll
    for (int i = 0; i < CC; ++i) {
        unsigned f = i * TPB + tid;          // 0..3583
        unsigned c = f / 14u;
        unsigned k = f - c * 14u;
        s_o[c * PAD + k] = out[base + f];
        s_g[c * PAD + k] = gt[base + f];
    }
    __syncthreads();

    const float* o = &s_o[tid * PAD];
    const float* g = &s_g[tid * PAD];

    float o0 = o[0], o1 = o[1], o2 = o[2], o3 = o[3], o4 = o[4];
    float o5 = o[5], o6 = o[6], o7 = o[7], o8 = o[8], o9 = o[9];
    float g0 = g[0], g1 = g[1], g2 = g[2], g3 = g[3], g4 = g[4];
    float g5 = g[5], g6 = g[6], g7 = g[7], g8 = g[8], g9 = g[9];

    float obj   = (g4 > 0.0f) ? 1.0f : 0.0f;
    float noobj = 1.0f - obj;

    // IoU of each predicted box vs gt box 0 (the reference's gt_ref)
    float iou0 = iou_f(o0, o1, o2, o3, g0, g1, g2, g3);
    float iou1 = iou_f(o5, o6, o7, o8, g0, g1, g2, g3);

    // jnp.argmax tie-break: first index wins -> select box 1 only if strictly greater
    bool  sel1    = (iou1 > iou0);
    float max_iou = sel1 ? iou1 : iou0;

    float pr0 = sel1 ? o5 : o0;
    float pr1 = sel1 ? o6 : o1;
    float pr2 = sel1 ? o7 : o2;
    float pr3 = sel1 ? o8 : o3;
    float pr4 = sel1 ? o9 : o4;
    float po4 = sel1 ? o4 : o9;          // pred_other conf

    float gr0 = sel1 ? g5 : g0;
    float gr1 = sel1 ? g6 : g1;
    float gr2 = sel1 ? g7 : g2;
    float gr3 = sel1 ? g8 : g3;
    float go4 = sel1 ? g4 : g9;          // gt_other conf

    float d4 = o4 - g4, d9 = o9 - g9;
    float no_loss = noobj * (d4 * d4 + d9 * d9);

    float ec = pr4 - max_iou;
    float conf_loss = ec * ec;

    float l0 = pr0 - gr0, l1 = pr1 - gr1, l2 = pr2 - gr2, l3 = pr3 - gr3;
    float loc_loss = l0 * l0 + l1 * l1 + l2 * l2 + l3 * l3;

    float eo = po4 - go4;
    float nbc_loss = eo * eo;

    float c0 = o[10] - g[10], c1 = o[11] - g[11], c2 = o[12] - g[12], c3 = o[13] - g[13];
    float cls_loss = c0 * c0 + c1 * c1 + c2 * c2 + c3 * c3;

    float cell = LAMBDA_NOOBJ * no_loss
               + obj * (conf_loss + LAMBDA_COORD * loc_loss
                        + LAMBDA_NOOBJ * nbc_loss + LAMBDA_CLASS * cls_loss);

    // Fixed-order block reduction (deterministic)
    red[tid] = cell;
    __syncthreads();
#pragma unroll
    for (int s = TPB / 2; s > 0; s >>= 1) {
        if (tid < (unsigned)s) red[tid] += red[tid + s];
        __syncthreads();
    }
    if (tid == 0) g_partials[tile] = red[0];
}

__global__ void __launch_bounds__(TPB)
yolo_reduce_kernel(float* __restrict__ d_out) {
    __shared__ double red[TPB];
    const unsigned tid = threadIdx.x;
    double acc = 0.0;
    for (int i = tid; i < TILES; i += TPB) acc += (double)g_partials[i];
    red[tid] = acc;
    __syncthreads();
#pragma unroll
    for (int s = TPB / 2; s > 0; s >>= 1) {
        if (tid < (unsigned)s) red[tid] += red[tid + s];
        __syncthreads();
    }
    if (tid == 0) d_out[0] = (float)(red[0] / (double)NIMG);
}

extern "C" void kernel_launch(void* const* d_in, const int* in_sizes, int n_in,
                              void* d_out, int out_size) {
    const float* output = (const float*)d_in[0];
    const float* gtruth = (const float*)d_in[1];
    float* outp = (float*)d_out;

    yolo_cell_kernel<<<TILES, TPB>>>(output, gtruth);
    yolo_reduce_kernel<<<1, TPB>>>(outp);
}